// round 17
// baseline (speedup 1.0000x reference)
#include <cuda_runtime.h>
#include <cuda_bf16.h>
#include <math.h>

#define T_FRAMES 256
#define NDET     16
#define HDIM     256
#define DHEAD    32
#define WINR     8
#define NTOK     16384       // 4*256*16
#define FFN      1024
#define QKVN     768
#define TG       4           // t per attn block
#define MB       320         // (TG-1 + 17) * 16 keys
#define PST      328         // P row stride (halfs)

// fp32 scratch
__device__ float g_c[NTOK * HDIM];
__device__ float g_y[NTOK * HDIM];
__device__ float g_z[NTOK * HDIM];
__device__ float g_bqkv[QKVN];
// bf16 scratch
__device__ __nv_bfloat16 g_xb[NTOK * HDIM];
__device__ __nv_bfloat16 g_qkv[NTOK * QKVN];
__device__ __nv_bfloat16 g_y16[NTOK * HDIM];
__device__ __nv_bfloat16 g_h16[NTOK * FFN];
__device__ __nv_bfloat16 g_wqkv[HDIM * QKVN];
__device__ __nv_bfloat16 g_w1[HDIM * FFN];
__device__ __nv_bfloat16 g_w2[FFN * HDIM];

__device__ __forceinline__ void mma_bf16(float c[4],
    unsigned a0, unsigned a1, unsigned a2, unsigned a3, unsigned b0, unsigned b1) {
    asm volatile(
        "mma.sync.aligned.m16n8k16.row.col.f32.bf16.bf16.f32 "
        "{%0,%1,%2,%3}, {%4,%5,%6,%7}, {%8,%9}, {%0,%1,%2,%3};\n"
        : "+f"(c[0]), "+f"(c[1]), "+f"(c[2]), "+f"(c[3])
        : "r"(a0), "r"(a1), "r"(a2), "r"(a3), "r"(b0), "r"(b1));
}
__device__ __forceinline__ void ldsm_x4(unsigned& r0, unsigned& r1, unsigned& r2, unsigned& r3,
                                        unsigned addr) {
    asm volatile("ldmatrix.sync.aligned.m8n8.x4.shared.b16 {%0,%1,%2,%3}, [%4];"
                 : "=r"(r0), "=r"(r1), "=r"(r2), "=r"(r3) : "r"(addr));
}
__device__ __forceinline__ void ldsm_x4t(unsigned& r0, unsigned& r1, unsigned& r2, unsigned& r3,
                                         unsigned addr) {
    asm volatile("ldmatrix.sync.aligned.m8n8.x4.trans.shared.b16 {%0,%1,%2,%3}, [%4];"
                 : "=r"(r0), "=r"(r1), "=r"(r2), "=r"(r3) : "r"(addr));
}
__device__ __forceinline__ void ldsm_x2(unsigned& r0, unsigned& r1, unsigned addr) {
    asm volatile("ldmatrix.sync.aligned.m8n8.x2.shared.b16 {%0,%1}, [%2];"
                 : "=r"(r0), "=r"(r1) : "r"(addr));
}
__device__ __forceinline__ void ldsm_x2t(unsigned& r0, unsigned& r1, unsigned addr) {
    asm volatile("ldmatrix.sync.aligned.m8n8.x2.trans.shared.b16 {%0,%1}, [%2];"
                 : "=r"(r0), "=r"(r1) : "r"(addr));
}
__device__ __forceinline__ void cp16(unsigned saddr, const void* gaddr) {
    asm volatile("cp.async.cg.shared.global [%0], [%1], 16;\n"
                 :: "r"(saddr), "l"(gaddr));
}
#define CP_COMMIT() asm volatile("cp.async.commit_group;\n" ::: "memory")
#define CP_WAIT2()  asm volatile("cp.async.wait_group 2;\n" ::: "memory")

__device__ __forceinline__ void store2(float* p, float a, float b) {
    *(float2*)p = make_float2(a, b);
}
__device__ __forceinline__ void store2(__nv_bfloat16* p, float a, float b) {
    *(__nv_bfloat162*)p = __floats2bfloat162_rn(a, b);
}

// ---- fp32 -> bf16 conversion: up to 3 tensors via blockIdx.y ----
__global__ __launch_bounds__(256) void cvt3_kernel(
    const float* __restrict__ a, const float* __restrict__ b, const float* __restrict__ c,
    __nv_bfloat16* oa, __nv_bfloat16* ob, __nv_bfloat16* oc, int n)
{
    const float* src = (blockIdx.y == 0) ? a : (blockIdx.y == 1) ? b : c;
    __nv_bfloat16* dst = (blockIdx.y == 0) ? oa : (blockIdx.y == 1) ? ob : oc;
    int i = (blockIdx.x * 256 + threadIdx.x) << 2;
    if (i < n) {
        float4 v = *(const float4*)(src + i);
        *(__nv_bfloat162*)(dst + i)     = __floats2bfloat162_rn(v.x, v.y);
        *(__nv_bfloat162*)(dst + i + 2) = __floats2bfloat162_rn(v.z, v.w);
    }
}

// ---- pack Wq*qs | Wk | Wv -> [HDIM][768] bf16, bias likewise ----
__global__ __launch_bounds__(256) void pack_qkv_kernel(
    const float* __restrict__ Wq, const float* __restrict__ Wk, const float* __restrict__ Wv,
    const float* __restrict__ bq, const float* __restrict__ bk, const float* __restrict__ bv,
    __nv_bfloat16* __restrict__ w, float* __restrict__ bias)
{
    const float qs = 0.17677669529663687f; // 1/sqrt(32)
    int i = (blockIdx.x * 256 + threadIdx.x) << 2;
    if (i < HDIM * HDIM) {
        int krow = i >> 8, j = i & 255;
        __nv_bfloat16* wr = w + krow * QKVN + j;
        float4 a = *(const float4*)(Wq + i);
        *(__nv_bfloat162*)(wr)     = __floats2bfloat162_rn(a.x * qs, a.y * qs);
        *(__nv_bfloat162*)(wr + 2) = __floats2bfloat162_rn(a.z * qs, a.w * qs);
        float4 bb = *(const float4*)(Wk + i);
        *(__nv_bfloat162*)(wr + 256)     = __floats2bfloat162_rn(bb.x, bb.y);
        *(__nv_bfloat162*)(wr + 256 + 2) = __floats2bfloat162_rn(bb.z, bb.w);
        float4 cc = *(const float4*)(Wv + i);
        *(__nv_bfloat162*)(wr + 512)     = __floats2bfloat162_rn(cc.x, cc.y);
        *(__nv_bfloat162*)(wr + 512 + 2) = __floats2bfloat162_rn(cc.z, cc.w);
    }
    if (blockIdx.x == 0 && threadIdx.x < 64) {
        int j = threadIdx.x << 2;
        float4 v = *(const float4*)(bq + j);
        *(float4*)(bias + j) = make_float4(v.x * qs, v.y * qs, v.z * qs, v.w * qs);
        *(float4*)(bias + 256 + j) = *(const float4*)(bk + j);
        *(float4*)(bias + 512 + j) = *(const float4*)(bv + j);
    }
}

// ---------------- bf16 TC GEMM: BM=128 BN=128 BK=32, warp tile 32x64 ----------------
// 4-stage cp.async (3 groups in flight), 1 barrier/ktile.
#define AS_STAGE 10240          // 128*40*2
#define BS_STAGE 8704           // 32*136*2
#define BS_BASE  40960          // 4*AS_STAGE
#define GEMM_SMEM_BYTES (BS_BASE + 4 * BS_STAGE)   // 75776

template <bool RELU, typename OutT>
__global__ __launch_bounds__(256, 2) void gemm_cp(
    const __nv_bfloat16* __restrict__ A, const __nv_bfloat16* __restrict__ B,
    const float* __restrict__ bias, OutT* __restrict__ C,
    int M, int N, int K)
{
    extern __shared__ char gsm[];
    const unsigned asb = (unsigned)__cvta_generic_to_shared(gsm);
    const unsigned bsb = asb + BS_BASE;

    const int tid = threadIdx.x;
    const int warp = tid >> 5, lane = tid & 31;
    const int wm = (warp >> 1) << 5;      // 0,32,64,96
    const int wn = (warp & 1) << 6;       // 0,64
    const int gm0 = blockIdx.y << 7;
    const int gn0 = blockIdx.x << 7;

    const int arow = tid >> 1;
    const int ac16a = (tid & 1) << 1;
    const int brow = tid >> 3;
    const int bc = tid & 7;

    const unsigned a_sdst = asb + ((arow * 40 + (ac16a << 3)) << 1);
    const unsigned b_sdst = bsb + ((brow * 136 + (bc << 3)) << 1);
    const __nv_bfloat16* a_gsrc = A + (long)(gm0 + arow) * K + (ac16a << 3);
    const __nv_bfloat16* b_gsrc = B + (long)brow * N + gn0 + (bc << 3);

    const unsigned abase = asb + (((wm + (lane & 15)) * 40 + ((lane >> 4) << 3)) << 1);
    const unsigned bbase = bsb + (((lane & 15) * 136 + wn + ((lane >> 4) << 3)) << 1);

    float acc[2][8][4];
#pragma unroll
    for (int i = 0; i < 2; i++)
#pragma unroll
        for (int j = 0; j < 8; j++)
#pragma unroll
            for (int l = 0; l < 4; l++) acc[i][j][l] = 0.f;

    const int nk = K >> 5;

    // prologue: stages 0,1,2
#pragma unroll
    for (int s = 0; s < 3; s++) {
        const __nv_bfloat16* ag = a_gsrc + s * 32;
        const __nv_bfloat16* bg = b_gsrc + (long)s * 32 * N;
        cp16(a_sdst + s * AS_STAGE,      ag);
        cp16(a_sdst + s * AS_STAGE + 16, ag + 8);
        cp16(b_sdst + s * BS_STAGE,       bg);
        cp16(b_sdst + s * BS_STAGE + 128, bg + 64);
        CP_COMMIT();
    }

    for (int kt = 0; kt < nk; kt++) {
        const int sc = kt & 3;
        CP_WAIT2();              // stage kt landed; kt+1, kt+2 may be pending
        __syncthreads();         // stage kt-1 readers done -> slot (kt+3)&3 free
        if (kt + 3 < nk) {
            const int sp = (kt + 3) & 3;
            const __nv_bfloat16* ag = a_gsrc + (kt + 3) * 32;
            const __nv_bfloat16* bg = b_gsrc + (long)(kt + 3) * 32 * N;
            cp16(a_sdst + sp * AS_STAGE,      ag);
            cp16(a_sdst + sp * AS_STAGE + 16, ag + 8);
            cp16(b_sdst + sp * BS_STAGE,       bg);
            cp16(b_sdst + sp * BS_STAGE + 128, bg + 64);
        }
        CP_COMMIT();

        const unsigned ab = abase + sc * AS_STAGE;
        const unsigned bb = bbase + sc * BS_STAGE;

        unsigned af[2][2][4];   // [ks][mt][4]
        unsigned bf[2][4][4];   // [ks][nt][4]
#pragma unroll
        for (int ks = 0; ks < 2; ks++) {
            ldsm_x4(af[ks][0][0], af[ks][0][1], af[ks][0][2], af[ks][0][3],
                    ab + ks * 32);
            ldsm_x4(af[ks][1][0], af[ks][1][1], af[ks][1][2], af[ks][1][3],
                    ab + 1280 + ks * 32);
        }
#pragma unroll
        for (int ks = 0; ks < 2; ks++)
#pragma unroll
            for (int nt = 0; nt < 4; nt++)
                ldsm_x4t(bf[ks][nt][0], bf[ks][nt][1], bf[ks][nt][2], bf[ks][nt][3],
                         bb + ks * 4352 + nt * 32);

#pragma unroll
        for (int ks = 0; ks < 2; ks++)
#pragma unroll
            for (int mt = 0; mt < 2; mt++)
#pragma unroll
                for (int nt = 0; nt < 4; nt++) {
                    mma_bf16(acc[mt][nt * 2],
                             af[ks][mt][0], af[ks][mt][1], af[ks][mt][2], af[ks][mt][3],
                             bf[ks][nt][0], bf[ks][nt][1]);
                    mma_bf16(acc[mt][nt * 2 + 1],
                             af[ks][mt][0], af[ks][mt][1], af[ks][mt][2], af[ks][mt][3],
                             bf[ks][nt][2], bf[ks][nt][3]);
                }
    }

#pragma unroll
    for (int mt = 0; mt < 2; mt++) {
        int row = gm0 + wm + (mt << 4) + (lane >> 2);
#pragma unroll
        for (int j = 0; j < 8; j++) {
            int col = gn0 + wn + (j << 3) + ((lane & 3) << 1);
            float b0 = bias[col], b1 = bias[col + 1];
            float v0 = acc[mt][j][0] + b0;
            float v1 = acc[mt][j][1] + b1;
            float v2 = acc[mt][j][2] + b0;
            float v3 = acc[mt][j][3] + b1;
            if (RELU) {
                v0 = fmaxf(v0, 0.f); v1 = fmaxf(v1, 0.f);
                v2 = fmaxf(v2, 0.f); v3 = fmaxf(v3, 0.f);
            }
            store2(C + (long)row * N + col, v0, v1);
            store2(C + (long)(row + 8) * N + col, v2, v3);
        }
    }
}

// ---------------- windowed attention: 4 t per block ----------------
#define KB_OFF   0
#define VB_OFF   25600
#define QB_OFF   51200
#define PB_OFF   56320
#define MASK_OFF 98304
#define RINV_OFF 99584
#define ATTN_SMEM_BYTES 99840

__global__ __launch_bounds__(256) void attn_kernel(
    const __nv_bfloat16* __restrict__ qkv, const unsigned char* __restrict__ kpm,
    float* __restrict__ ctx)
{
    extern __shared__ char smc[];
    __nv_bfloat16* Pb = (__nv_bfloat16*)(smc + PB_OFF);
    float* maskadd = (float*)(smc + MASK_OFF);
    float* rowinv  = (float*)(smc + RINV_OFF);

    const unsigned sbase = (unsigned)__cvta_generic_to_shared(smc);
    const int tid = threadIdx.x;
    const int w = tid >> 5, lane = tid & 31;
    const int t0 = blockIdx.x << 2, b = blockIdx.y, h = blockIdx.z;

    for (int slot = tid; slot < 4 * MB; slot += 256) {
        int m = slot >> 2, k8 = slot & 3;
        int f = t0 + (m >> 4) - WINR;
        int n = m & 15;
        uint4 kv = make_uint4(0, 0, 0, 0), vv = make_uint4(0, 0, 0, 0);
        if (f >= 0 && f < T_FRAMES) {
            long base = ((long)((b * T_FRAMES + f) * NDET + n)) * QKVN + h * DHEAD + (k8 << 3);
            kv = *(const uint4*)(qkv + base + 256);
            vv = *(const uint4*)(qkv + base + 512);
        }
        *(uint4*)((__nv_bfloat16*)(smc + KB_OFF) + m * 40 + (k8 << 3)) = kv;
        *(uint4*)((__nv_bfloat16*)(smc + VB_OFF) + m * 40 + (k8 << 3)) = vv;
    }
    {
        int r = tid >> 2, k8 = tid & 3;
        long tok = (long)(b * T_FRAMES + t0 + (r >> 4)) * NDET + (r & 15);
        *(uint4*)((__nv_bfloat16*)(smc + QB_OFF) + r * 40 + (k8 << 3)) =
            *(const uint4*)(qkv + tok * QKVN + h * DHEAD + (k8 << 3));
    }
    for (int m = tid; m < MB; m += 256) {
        int f = t0 + (m >> 4) - WINR;
        int n = m & 15;
        bool ok = (f >= 0) && (f < T_FRAMES) &&
                  (kpm[(b * T_FRAMES + f) * NDET + n] == 0);
        maskadd[m] = ok ? 0.f : -1e30f;
    }
    __syncthreads();

    // logits: Pb[64][320] = Q @ K^T
    {
        unsigned qa[4][2][4];
#pragma unroll
        for (int qt = 0; qt < 4; qt++) {
            unsigned qaddr = sbase + QB_OFF +
                ((((qt << 4) + (lane & 15)) * 40 + ((lane >> 4) << 3)) << 1);
            ldsm_x4(qa[qt][0][0], qa[qt][0][1], qa[qt][0][2], qa[qt][0][3], qaddr);
            ldsm_x4(qa[qt][1][0], qa[qt][1][1], qa[qt][1][2], qa[qt][1][3], qaddr + 32);
        }
        const int m0w = w * 40;
        const int lr = lane & 7;
        const int hg = (lane >> 3) & 1;
#pragma unroll
        for (int mt = 0; mt < 5; mt++) {
            int m0 = m0w + (mt << 3);
            unsigned baddr = sbase + KB_OFF + (((m0 + lr) * 40 + (hg << 3)) << 1);
            unsigned b0, b1, b2, b3;
            ldsm_x2(b0, b1, baddr);
            ldsm_x2(b2, b3, baddr + 32);
#pragma unroll
            for (int qt = 0; qt < 4; qt++) {
                float c[4] = {0.f, 0.f, 0.f, 0.f};
                mma_bf16(c, qa[qt][0][0], qa[qt][0][1], qa[qt][0][2], qa[qt][0][3], b0, b1);
                mma_bf16(c, qa[qt][1][0], qa[qt][1][1], qa[qt][1][2], qa[qt][1][3], b2, b3);
                int row = (qt << 4) + (lane >> 2), mc = m0 + ((lane & 3) << 1);
                *(__nv_bfloat162*)(Pb + row * PST + mc)       = __floats2bfloat162_rn(c[0], c[1]);
                *(__nv_bfloat162*)(Pb + (row + 8) * PST + mc) = __floats2bfloat162_rn(c[2], c[3]);
            }
        }
    }
    __syncthreads();

    // masked softmax per row (4 lanes/row); valid window = [16*tloc, 16*tloc+272)
    {
        const int r = tid >> 2, l4 = tid & 3;
        const int p0 = (r >> 4) << 3;
        const int p1 = p0 + 136;
        float mx = -1e30f;
        for (int p = p0 + l4; p < p1; p += 4) {
            float2 v = __bfloat1622float2(*(__nv_bfloat162*)(Pb + r * PST + (p << 1)));
            float2 ma = *(float2*)(maskadd + (p << 1));
            mx = fmaxf(mx, fmaxf(v.x + ma.x, v.y + ma.y));
        }
        mx = fmaxf(mx, __shfl_xor_sync(0xffffffffu, mx, 1));
        mx = fmaxf(mx, __shfl_xor_sync(0xffffffffu, mx, 2));
        float sum = 0.f;
        for (int p = l4; p < 160; p += 4) {
            float e0 = 0.f, e1 = 0.f;
            if (p >= p0 && p < p1) {
                float2 v = __bfloat1622float2(*(__nv_bfloat162*)(Pb + r * PST + (p << 1)));
                float2 ma = *(float2*)(maskadd + (p << 1));
                e0 = __expf(v.x + ma.x - mx);
                e1 = __expf(v.y + ma.y - mx);
                sum += e0 + e1;
            }
            *(__nv_bfloat162*)(Pb + r * PST + (p << 1)) = __floats2bfloat162_rn(e0, e1);
        }
        sum += __shfl_xor_sync(0xffffffffu, sum, 1);
        sum += __shfl_xor_sync(0xffffffffu, sum, 2);
        if (l4 == 0) rowinv[r] = 1.0f / sum;
    }
    __syncthreads();

    // PV: ctx[64][32] = Pb @ Vb; warp owns 16 rows x 16 cols, full k
    {
        const int mrow = (w >> 1) << 4;
        const int nc0  = (w & 1) << 4;
        float c0[4] = {0.f, 0.f, 0.f, 0.f};
        float c1[4] = {0.f, 0.f, 0.f, 0.f};
#pragma unroll 5
        for (int ks = 0; ks < 20; ks++) {
            unsigned aaddr = sbase + PB_OFF +
                (((mrow + (lane & 15)) * PST + (ks << 4) + ((lane >> 4) << 3)) << 1);
            unsigned a0, a1, a2, a3;
            ldsm_x4(a0, a1, a2, a3, aaddr);
            unsigned baddr = sbase + VB_OFF + ((((ks << 4) + (lane & 15)) * 40 + nc0) << 1);
            unsigned b0, b1, b2, b3;
            ldsm_x2t(b0, b1, baddr);
            ldsm_x2t(b2, b3, baddr + 16);
            mma_bf16(c0, a0, a1, a2, a3, b0, b1);
            mma_bf16(c1, a0, a1, a2, a3, b2, b3);
        }
        const int rr = mrow + (lane >> 2);
        const int cc = nc0 + ((lane & 3) << 1);
        const float ri0 = rowinv[rr], ri1 = rowinv[rr + 8];
        long tok0 = (long)(b * T_FRAMES + t0 + (rr >> 4)) * NDET + (rr & 15);
        int r8 = rr + 8;
        long tok1 = (long)(b * T_FRAMES + t0 + (r8 >> 4)) * NDET + (r8 & 15);
        float* o0 = ctx + tok0 * HDIM + h * DHEAD + cc;
        float* o1 = ctx + tok1 * HDIM + h * DHEAD + cc;
        store2(o0,     c0[0] * ri0, c0[1] * ri0);
        store2(o0 + 8, c1[0] * ri0, c1[1] * ri0);
        store2(o1,     c0[2] * ri1, c0[3] * ri1);
        store2(o1 + 8, c1[2] * ri1, c1[3] * ri1);
    }
}

// residual add + LayerNorm; optional fused bf16 output copy
template <bool DUAL>
__global__ __launch_bounds__(256) void add_ln_kernel(
    const float* __restrict__ A, const float* __restrict__ Bv,
    const float* __restrict__ gw, const float* __restrict__ bw,
    float* __restrict__ out, __nv_bfloat16* __restrict__ out16)
{
    const int tok  = (blockIdx.x << 3) + (threadIdx.x >> 5);
    const int lane = threadIdx.x & 31;
    const float4* a4 = (const float4*)(A  + (long)tok * HDIM);
    const float4* b4 = (const float4*)(Bv + (long)tok * HDIM);
    float4 p0 = a4[lane * 2], p1 = a4[lane * 2 + 1];
    float4 q0 = b4[lane * 2], q1 = b4[lane * 2 + 1];
    float vv[8] = { p0.x + q0.x, p0.y + q0.y, p0.z + q0.z, p0.w + q0.w,
                    p1.x + q1.x, p1.y + q1.y, p1.z + q1.z, p1.w + q1.w };
    float s = 0.f;
#pragma unroll
    for (int i = 0; i < 8; i++) s += vv[i];
#pragma unroll
    for (int o = 16; o; o >>= 1) s += __shfl_xor_sync(0xffffffffu, s, o);
    const float mean = s * (1.f / 256.f);
    float vs = 0.f;
#pragma unroll
    for (int i = 0; i < 8; i++) { float d = vv[i] - mean; vs += d * d; }
#pragma unroll
    for (int o = 16; o; o >>= 1) vs += __shfl_xor_sync(0xffffffffu, vs, o);
    const float rs = rsqrtf(vs * (1.f / 256.f) + 1e-5f);

    float4 g0 = ((const float4*)gw)[lane * 2], g1 = ((const float4*)gw)[lane * 2 + 1];
    float4 e0 = ((const float4*)bw)[lane * 2], e1 = ((const float4*)bw)[lane * 2 + 1];
    float r[8];
    r[0] = (vv[0]-mean)*rs*g0.x + e0.x;  r[1] = (vv[1]-mean)*rs*g0.y + e0.y;
    r[2] = (vv[2]-mean)*rs*g0.z + e0.z;  r[3] = (vv[3]-mean)*rs*g0.w + e0.w;
    r[4] = (vv[4]-mean)*rs*g1.x + e1.x;  r[5] = (vv[5]-mean)*rs*g1.y + e1.y;
    r[6] = (vv[6]-mean)*rs*g1.z + e1.z;  r[7] = (vv[7]-mean)*rs*g1.w + e1.w;
    float4* o4 = (float4*)(out + (long)tok * HDIM);
    o4[lane * 2]     = make_float4(r[0], r[1], r[2], r[3]);
    o4[lane * 2 + 1] = make_float4(r[4], r[5], r[6], r[7]);
    if (DUAL) {
        __nv_bfloat16* ob = out16 + (long)tok * HDIM + lane * 8;
        __nv_bfloat162 hh[4];
        hh[0] = __floats2bfloat162_rn(r[0], r[1]);
        hh[1] = __floats2bfloat162_rn(r[2], r[3]);
        hh[2] = __floats2bfloat162_rn(r[4], r[5]);
        hh[3] = __floats2bfloat162_rn(r[6], r[7]);
        *(uint4*)ob = *(uint4*)&hh[0];
    }
}

extern "C" void kernel_launch(void* const* d_in, const int* in_sizes, int n_in,
                              void* d_out, int out_size)
{
    const float* x   = (const float*)d_in[0];
    const unsigned char* kpm = (const unsigned char*)d_in[1];
    const float* Wq = (const float*)d_in[2];
    const float* bq = (const float*)d_in[3];
    const float* Wk = (const float*)d_in[4];
    const float* bk = (const float*)d_in[5];
    const float* Wv = (const float*)d_in[6];
    const float* bv = (const float*)d_in[7];
    const float* W1 = (const float*)d_in[8];
    const float* b1 = (const float*)d_in[9];
    const float* W2 = (const float*)d_in[10];
    const float* b2 = (const float*)d_in[11];
    const float* g1 = (const float*)d_in[12];
    const float* be1 = (const float*)d_in[13];
    const float* g2 = (const float*)d_in[14];
    const float* be2 = (const float*)d_in[15];
    float* out = (float*)d_out;

    float *cb, *yb, *zb, *bqkv;
    __nv_bfloat16 *xb, *qkvb, *y16, *h16, *wqkvb, *w1b, *w2b;
    cudaGetSymbolAddress((void**)&cb, g_c);
    cudaGetSymbolAddress((void**)&yb, g_y);
    cudaGetSymbolAddress((void**)&zb, g_z);
    cudaGetSymbolAddress((void**)&bqkv, g_bqkv);
    cudaGetSymbolAddress((void**)&xb, g_xb);
    cudaGetSymbolAddress((void**)&qkvb, g_qkv);
    cudaGetSymbolAddress((void**)&y16, g_y16);
    cudaGetSymbolAddress((void**)&h16, g_h16);
    cudaGetSymbolAddress((void**)&wqkvb, g_wqkv);
    cudaGetSymbolAddress((void**)&w1b, g_w1);
    cudaGetSymbolAddress((void**)&w2b, g_w2);

    cudaFuncSetAttribute(attn_kernel,
                         cudaFuncAttributeMaxDynamicSharedMemorySize, ATTN_SMEM_BYTES);
    cudaFuncSetAttribute(gemm_cp<false, __nv_bfloat16>,
                         cudaFuncAttributeMaxDynamicSharedMemorySize, GEMM_SMEM_BYTES);
    cudaFuncSetAttribute(gemm_cp<true, __nv_bfloat16>,
                         cudaFuncAttributeMaxDynamicSharedMemorySize, GEMM_SMEM_BYTES);
    cudaFuncSetAttribute(gemm_cp<false, float>,
                         cudaFuncAttributeMaxDynamicSharedMemorySize, GEMM_SMEM_BYTES);

    dim3 blk(256);

    cvt3_kernel<<<dim3(NTOK * HDIM / 1024, 1), blk>>>(x, x, x, xb, xb, xb, NTOK * HDIM);
    pack_qkv_kernel<<<HDIM * HDIM / 1024, blk>>>(Wq, Wk, Wv, bq, bk, bv, wqkvb, bqkv);
    cvt3_kernel<<<dim3(HDIM * FFN / 1024, 2), blk>>>(W1, W2, W1, w1b, w2b, w1b, HDIM * FFN);

    gemm_cp<false, __nv_bfloat16><<<dim3(QKVN / 128, NTOK / 128), blk, GEMM_SMEM_BYTES>>>(
        xb, wqkvb, bqkv, qkvb, NTOK, QKVN, HDIM);

    dim3 gAttn(T_FRAMES / TG, 4, 8);
    attn_kernel<<<gAttn, blk, ATTN_SMEM_BYTES>>>(qkvb, kpm, cb);

    add_ln_kernel<true><<<NTOK / 8, blk>>>(x, cb, g1, be1, yb, y16);

    gemm_cp<true,  __nv_bfloat16><<<dim3(FFN / 128, NTOK / 128), blk, GEMM_SMEM_BYTES>>>(
        y16, w1b, b1, h16, NTOK, FFN, HDIM);
    gemm_cp<false, float><<<dim3(HDIM / 128, NTOK / 128), blk, GEMM_SMEM_BYTES>>>(
        h16, w2b, b2, zb, NTOK, HDIM, FFN);

    add_ln_kernel<false><<<NTOK / 8, blk>>>(yb, zb, g2, be2, out, nullptr);
}